// round 1
// baseline (speedup 1.0000x reference)
#include <cuda_runtime.h>
#include <cstdint>
#include <cstddef>

#define T_STEPS 1024
#define BATCH   64
#define INDIM   512
#define HID     512
#define G3      1536   // 3*HID

// ---------------------------------------------------------------------------
// Global scratch (static __device__ arrays: the allowed allocation mechanism)
// ---------------------------------------------------------------------------
__device__ float g_gi[(size_t)T_STEPS * BATCH * G3];   // 402 MB: gi = x@W_ih^T + b_ih, layout [t*64+b][3H]
__device__ float g_h[2][HID * BATCH];                  // recurrent state, TRANSPOSED layout [hid][batch]
__device__ unsigned g_count;                           // grid barrier arrival counter
__device__ unsigned g_phase;                           // grid barrier release generation

__global__ void reset_barrier_kernel() {
    g_count = 0u;
    g_phase = 0u;
}

// ---------------------------------------------------------------------------
// Phase 1: gi[m][n] = sum_k X[m][k] * W_ih[n][k] + b_ih[n]
// M = 65536, N = 1536, K = 512.  Classic 128x128x8 SGEMM, 8x8 microtile.
// ---------------------------------------------------------------------------
__global__ __launch_bounds__(256, 2) void gi_gemm_kernel(
    const float* __restrict__ X,
    const float* __restrict__ W,
    const float* __restrict__ bias)
{
    __shared__ float As[8][128];
    __shared__ float Bs[8][128];

    const int tid = threadIdx.x;
    const int tx  = tid & 15;        // n direction
    const int ty  = tid >> 4;        // m direction
    const int M0  = blockIdx.y * 128;
    const int N0  = blockIdx.x * 128;

    const int lrow = tid >> 1;          // 0..127
    const int lcol = (tid & 1) * 4;     // 0 or 4
    const float* Aptr = X + (size_t)(M0 + lrow) * INDIM + lcol;
    const float* Bptr = W + (size_t)(N0 + lrow) * INDIM + lcol;

    float acc[8][8];
#pragma unroll
    for (int i = 0; i < 8; ++i)
#pragma unroll
        for (int j = 0; j < 8; ++j) acc[i][j] = 0.0f;

    float4 ra = *(const float4*)Aptr;
    float4 rb = *(const float4*)Bptr;

    for (int kt = 0; kt < 64; ++kt) {
        As[lcol + 0][lrow] = ra.x;
        As[lcol + 1][lrow] = ra.y;
        As[lcol + 2][lrow] = ra.z;
        As[lcol + 3][lrow] = ra.w;
        Bs[lcol + 0][lrow] = rb.x;
        Bs[lcol + 1][lrow] = rb.y;
        Bs[lcol + 2][lrow] = rb.z;
        Bs[lcol + 3][lrow] = rb.w;
        __syncthreads();

        if (kt < 63) {
            ra = *(const float4*)(Aptr + (kt + 1) * 8);
            rb = *(const float4*)(Bptr + (kt + 1) * 8);
        }

#pragma unroll
        for (int k = 0; k < 8; ++k) {
            float a[8], b[8];
            *(float4*)&a[0] = *(const float4*)&As[k][ty * 4];
            *(float4*)&a[4] = *(const float4*)&As[k][64 + ty * 4];
            *(float4*)&b[0] = *(const float4*)&Bs[k][tx * 4];
            *(float4*)&b[4] = *(const float4*)&Bs[k][64 + tx * 4];
#pragma unroll
            for (int i = 0; i < 8; ++i)
#pragma unroll
                for (int j = 0; j < 8; ++j)
                    acc[i][j] += a[i] * b[j];
        }
        __syncthreads();
    }

    const float4 bia0 = *(const float4*)&bias[N0 + tx * 4];
    const float4 bia1 = *(const float4*)&bias[N0 + 64 + tx * 4];

#pragma unroll
    for (int i = 0; i < 8; ++i) {
        const int row = M0 + ((i < 4) ? (ty * 4 + i) : (64 + ty * 4 + (i - 4)));
        float* o = g_gi + (size_t)row * G3 + N0;
        float4 v0, v1;
        v0.x = acc[i][0] + bia0.x; v0.y = acc[i][1] + bia0.y;
        v0.z = acc[i][2] + bia0.z; v0.w = acc[i][3] + bia0.w;
        v1.x = acc[i][4] + bia1.x; v1.y = acc[i][5] + bia1.y;
        v1.z = acc[i][6] + bia1.z; v1.w = acc[i][7] + bia1.w;
        *(float4*)(o + tx * 4)      = v0;
        *(float4*)(o + 64 + tx * 4) = v1;
    }
}

// ---------------------------------------------------------------------------
// Phase 2: persistent recurrent kernel
// ---------------------------------------------------------------------------
__device__ __forceinline__ void cp_async16(float4* dst_smem, const float4* src) {
    unsigned d = (unsigned)__cvta_generic_to_shared(dst_smem);
    asm volatile("cp.async.cg.shared.global [%0], [%1], 16;" :: "r"(d), "l"(src));
}

__device__ __forceinline__ float sigmoidf_(float x) {
    return 1.0f / (1.0f + expf(-x));
}

__device__ __forceinline__ void grid_barrier(unsigned target, unsigned nblocks) {
    __syncthreads();
    if (threadIdx.x == 0) {
        __threadfence();
        unsigned prev = atomicAdd(&g_count, 1u);
        if (prev == nblocks - 1u) {
            *(volatile unsigned*)&g_count = 0u;
            __threadfence();
            *(volatile unsigned*)&g_phase = target;   // release
        } else {
            while (*(volatile unsigned*)&g_phase < target) { }
        }
        __threadfence();
    }
    __syncthreads();
}

// grid = 128 blocks x 128 threads. Block owns 4 hidden units (jb..jb+3).
// Warp jl handles hidden unit jb+jl for all 64 batches (lane = batch pair).
// smem: sW[12][512] (r/z/n weight rows, persistent) | sh[512][64] (h stage,
// [hid][batch]) | sout[64][4] (output transpose)
__global__ __launch_bounds__(128, 1) void gru_recurrent_kernel(
    const float* __restrict__ paddings,
    const float* __restrict__ W_hh,
    const float* __restrict__ b_hh,
    float* __restrict__ out)
{
    extern __shared__ float smem[];
    float* sW   = smem;                       // 12*512 floats
    float* sh   = smem + 12 * 512;            // 512*64 floats
    float* sout = sh + HID * BATCH;           // 64*4 floats

    const int tid = threadIdx.x;
    const int jl  = tid >> 5;                 // warp id 0..3
    const int bg  = tid & 31;                 // lane = batch pair
    const int jb  = blockIdx.x * 4;
    const int hid = jb + jl;
    const unsigned nblocks = gridDim.x;

    // Load this block's 12 W_hh rows (r,z,n for jb..jb+3) into SMEM once.
    for (int i = tid; i < 12 * 128; i += 128) {
        const int r = i >> 7;                 // 0..11
        const int c = i & 127;                // float4 column
        const int grow = (r >> 2) * HID + jb + (r & 3);
        ((float4*)sW)[(size_t)r * 128 + c] =
            __ldg((const float4*)(W_hh + (size_t)grow * HID) + c);
    }
    const float bhr = __ldg(b_hh + hid);
    const float bhz = __ldg(b_hh + HID + hid);
    const float bhn = __ldg(b_hh + 2 * HID + hid);

    // h0 = 0 (each block zeroes its own 4 hidden rows of buffer 0)
    if (tid < 64) {
        float4 z4 = make_float4(0.f, 0.f, 0.f, 0.f);
        __stcg(((float4*)g_h[0]) + jb * 16 + tid, z4);
    }
    __threadfence();

    unsigned target = 1;
    grid_barrier(target, nblocks); ++target;

    int cur = 0;
    const float4* wr4 = (const float4*)(sW + (size_t)jl * 512);
    const float4* wz4 = (const float4*)(sW + (size_t)(4 + jl) * 512);
    const float4* wn4 = (const float4*)(sW + (size_t)(8 + jl) * 512);

    for (int t = 0; t < T_STEPS; ++t) {
        const int b0 = 2 * bg, b1 = b0 + 1;

        // Prefetch gi triplets + paddings early (latency hidden under compute)
        const float* gi_t = g_gi + (size_t)t * BATCH * G3;
        const float ir0 = __ldg(gi_t + (size_t)b0 * G3 + hid);
        const float iz0 = __ldg(gi_t + (size_t)b0 * G3 + HID + hid);
        const float in0 = __ldg(gi_t + (size_t)b0 * G3 + 2 * HID + hid);
        const float ir1 = __ldg(gi_t + (size_t)b1 * G3 + hid);
        const float iz1 = __ldg(gi_t + (size_t)b1 * G3 + HID + hid);
        const float in1 = __ldg(gi_t + (size_t)b1 * G3 + 2 * HID + hid);
        const float p0  = __ldg(paddings + t * BATCH + b0);
        const float p1  = __ldg(paddings + t * BATCH + b1);

        // Stage h (L2-coherent, L1-bypassing) in 4 pipelined chunks.
        const float4* hsrc = (const float4*)g_h[cur];
        float4* shd = (float4*)sh;
#pragma unroll
        for (int c = 0; c < 4; ++c) {
#pragma unroll
            for (int i = 0; i < 16; ++i) {
                const int idx = c * 2048 + i * 128 + tid;
                cp_async16(shd + idx, hsrc + idx);
            }
            asm volatile("cp.async.commit_group;");
        }

        float ar0 = 0.f, az0 = 0.f, an0 = 0.f;
        float ar1 = 0.f, az1 = 0.f, an1 = 0.f;
        const float2* h2 = ((const float2*)sh) + bg;

#pragma unroll
        for (int c = 0; c < 4; ++c) {
            if (c == 0)      asm volatile("cp.async.wait_group 3;");
            else if (c == 1) asm volatile("cp.async.wait_group 2;");
            else if (c == 2) asm volatile("cp.async.wait_group 1;");
            else             asm volatile("cp.async.wait_group 0;");
            __syncthreads();

            const int k4beg = c * 32;
#pragma unroll 4
            for (int k4 = k4beg; k4 < k4beg + 32; ++k4) {
                const float4 wr = wr4[k4];
                const float4 wz = wz4[k4];
                const float4 wn = wn4[k4];
                const float2 h0 = h2[(4 * k4 + 0) * 32];
                const float2 hA = h2[(4 * k4 + 1) * 32];
                const float2 hB = h2[(4 * k4 + 2) * 32];
                const float2 hC = h2[(4 * k4 + 3) * 32];
                ar0 += h0.x * wr.x; ar1 += h0.y * wr.x;
                az0 += h0.x * wz.x; az1 += h0.y * wz.x;
                an0 += h0.x * wn.x; an1 += h0.y * wn.x;
                ar0 += hA.x * wr.y; ar1 += hA.y * wr.y;
                az0 += hA.x * wz.y; az1 += hA.y * wz.y;
                an0 += hA.x * wn.y; an1 += hA.y * wn.y;
                ar0 += hB.x * wr.z; ar1 += hB.y * wr.z;
                az0 += hB.x * wz.z; az1 += hB.y * wz.z;
                an0 += hB.x * wn.z; an1 += hB.y * wn.z;
                ar0 += hC.x * wr.w; ar1 += hC.y * wr.w;
                az0 += hC.x * wz.w; az1 += hC.y * wz.w;
                an0 += hC.x * wn.w; an1 += hC.y * wn.w;
            }
        }

        // Gates + padding-aware carry.
        const float2 hp = *(const float2*)&sh[(size_t)hid * BATCH + b0];

        const float r0 = sigmoidf_(ir0 + ar0 + bhr);
        const float z0 = sigmoidf_(iz0 + az0 + bhz);
        const float n0 = tanhf(in0 + r0 * (an0 + bhn));
        const float hc0 = (1.f - z0) * n0 + z0 * hp.x;
        const float hn0 = p0 * hp.x + (1.f - p0) * hc0;

        const float r1 = sigmoidf_(ir1 + ar1 + bhr);
        const float z1 = sigmoidf_(iz1 + az1 + bhz);
        const float n1 = tanhf(in1 + r1 * (an1 + bhn));
        const float hc1 = (1.f - z1) * n1 + z1 * hp.y;
        const float hn1 = p1 * hp.y + (1.f - p1) * hc1;

        const int nxt = cur ^ 1;
        float2 hv; hv.x = hn0; hv.y = hn1;
        __stcg((float2*)&g_h[nxt][(size_t)hid * BATCH + b0], hv);

        sout[b0 * 4 + jl] = hn0;
        sout[b1 * 4 + jl] = hn1;
        __threadfence();      // make h_next globally visible before barrier
        __syncthreads();      // sout visible within block

        // Coalesced float4 output writes: outputs copy + states copy
        {
            const int copy = tid >> 6;       // 0 or 1
            const int b    = tid & 63;
            const float4 v = *(const float4*)&sout[b * 4];
            float* optr = out
                + (size_t)copy * ((size_t)BATCH * T_STEPS * HID)
                + (size_t)b * ((size_t)T_STEPS * HID)
                + (size_t)t * HID + jb;
            *(float4*)optr = v;
        }

        grid_barrier(target, nblocks); ++target;
        cur = nxt;
    }
}

// ---------------------------------------------------------------------------
// Launch
// ---------------------------------------------------------------------------
extern "C" void kernel_launch(void* const* d_in, const int* in_sizes, int n_in,
                              void* d_out, int out_size) {
    const float* x        = (const float*)d_in[0];   // [T,B,I]
    const float* paddings = (const float*)d_in[1];   // [T,B,1]
    const float* W_ih     = (const float*)d_in[2];   // [3H,I]
    const float* W_hh     = (const float*)d_in[3];   // [3H,H]
    const float* b_ih     = (const float*)d_in[4];   // [3H]
    const float* b_hh     = (const float*)d_in[5];   // [3H]
    float* out            = (float*)d_out;           // [2][B][T][H]

    const int smem_bytes = (12 * 512 + HID * BATCH + BATCH * 4) * sizeof(float); // 156,672 B
    cudaFuncSetAttribute(gru_recurrent_kernel,
                         cudaFuncAttributeMaxDynamicSharedMemorySize, smem_bytes);

    reset_barrier_kernel<<<1, 1>>>();

    dim3 gemm_grid(G3 / 128, (T_STEPS * BATCH) / 128);   // 12 x 512
    gi_gemm_kernel<<<gemm_grid, 256>>>(x, W_ih, b_ih);

    gru_recurrent_kernel<<<128, 128, smem_bytes>>>(paddings, W_hh, b_hh, out);
}

// round 5
// speedup vs baseline: 1.0860x; 1.0860x over previous
#include <cuda_runtime.h>
#include <cuda_bf16.h>
#include <cstdint>
#include <cstddef>

#define T_STEPS 1024
#define BATCH   64
#define INDIM   512
#define HID     512
#define G3      1536   // 3*HID
#define HB      (HID * BATCH)
#define TBROWS  (T_STEPS * BATCH)   // 65536 GEMM rows

// ---------------------------------------------------------------------------
// Global scratch (static __device__ arrays: the allowed allocation mechanism)
// ---------------------------------------------------------------------------
__device__ float         g_gi[(size_t)TBROWS * G3];          // 402 MB  gi[t*64+b][3H]
__device__ float         g_h[2][HB];                         // recurrent state, [hid][batch]
__device__ unsigned      g_count;                            // grid barrier arrival counter
__device__ unsigned      g_phase;                            // grid barrier release generation
__device__ __nv_bfloat16 g_a_hi[(size_t)TBROWS * INDIM];     // 64 MB
__device__ __nv_bfloat16 g_a_lo[(size_t)TBROWS * INDIM];     // 64 MB
__device__ __nv_bfloat16 g_w_hi[(size_t)G3 * INDIM];         // 1.5 MB
__device__ __nv_bfloat16 g_w_lo[(size_t)G3 * INDIM];         // 1.5 MB

__global__ void reset_barrier_kernel() {
    g_count = 0u;
    g_phase = 0u;
}

__device__ __forceinline__ uint32_t smem_u32(const void* p) {
    uint32_t a;
    asm("{ .reg .u64 t; cvta.to.shared.u64 t, %1; cvt.u32.u64 %0, t; }" : "=r"(a) : "l"(p));
    return a;
}

// ===========================================================================
// Pre-pass: split fp32 -> (bf16 hi, bf16 lo) planes
// ===========================================================================
__device__ __forceinline__ void split4(float4 v, uint2& hi, uint2& lo) {
    __nv_bfloat16 h0 = __float2bfloat16_rn(v.x), h1 = __float2bfloat16_rn(v.y);
    __nv_bfloat16 h2 = __float2bfloat16_rn(v.z), h3 = __float2bfloat16_rn(v.w);
    __nv_bfloat16 l0 = __float2bfloat16_rn(v.x - __bfloat162float(h0));
    __nv_bfloat16 l1 = __float2bfloat16_rn(v.y - __bfloat162float(h1));
    __nv_bfloat16 l2 = __float2bfloat16_rn(v.z - __bfloat162float(h2));
    __nv_bfloat16 l3 = __float2bfloat16_rn(v.w - __bfloat162float(h3));
    __nv_bfloat162 ph0; ph0.x = h0; ph0.y = h1;
    __nv_bfloat162 ph1; ph1.x = h2; ph1.y = h3;
    __nv_bfloat162 pl0; pl0.x = l0; pl0.y = l1;
    __nv_bfloat162 pl1; pl1.x = l2; pl1.y = l3;
    hi.x = *(uint32_t*)&ph0; hi.y = *(uint32_t*)&ph1;
    lo.x = *(uint32_t*)&pl0; lo.y = *(uint32_t*)&pl1;
}

__global__ __launch_bounds__(256) void convert_kernel(
    const float* __restrict__ X, const float* __restrict__ W)
{
    const size_t stride = (size_t)gridDim.x * 256;
    const size_t i0 = (size_t)blockIdx.x * 256 + threadIdx.x;

    const size_t nx = (size_t)TBROWS * INDIM / 4;
    for (size_t t = i0; t < nx; t += stride) {
        float4 v = __ldg((const float4*)X + t);
        uint2 hi, lo; split4(v, hi, lo);
        ((uint2*)g_a_hi)[t] = hi;
        ((uint2*)g_a_lo)[t] = lo;
    }
    const size_t nw = (size_t)G3 * INDIM / 4;
    for (size_t t = i0; t < nw; t += stride) {
        float4 v = __ldg((const float4*)W + t);
        uint2 hi, lo; split4(v, hi, lo);
        ((uint2*)g_w_hi)[t] = hi;
        ((uint2*)g_w_lo)[t] = lo;
    }
}

// ===========================================================================
// Phase 1: gi = X @ W_ih^T + b_ih, 3xBF16 mma.sync (no 'a'-target features)
// Tile 128x128x32, 3-stage cp.async pipeline, 8 warps (2M x 4N), 64x32/warp.
// smem: [stage][arr][128][40] bf16, arr = {Ahi, Alo, Bhi, Blo}; stride 40
// bf16 = 80 B rows (16B-aligned rows; 5r mod 8 permutes 16B groups).
// ===========================================================================
#define BK 32
#define SROW 40                         // bf16 row stride
#define ARR_ELEMS (128 * SROW)          // 5120 bf16 per array
#define GEMM_SMEM (3 * 4 * ARR_ELEMS * 2)   // 122880 B

#define LDSM4(r, a) asm volatile( \
    "ldmatrix.sync.aligned.m8n8.x4.shared.b16 {%0,%1,%2,%3}, [%4];" \
    : "=r"((r)[0]), "=r"((r)[1]), "=r"((r)[2]), "=r"((r)[3]) : "r"(a))
#define LDSM2(r, a) asm volatile( \
    "ldmatrix.sync.aligned.m8n8.x2.shared.b16 {%0,%1}, [%2];" \
    : "=r"((r)[0]), "=r"((r)[1]) : "r"(a))
#define MMA16816(d, a, b) asm volatile( \
    "mma.sync.aligned.m16n8k16.row.col.f32.bf16.bf16.f32 " \
    "{%0,%1,%2,%3}, {%4,%5,%6,%7}, {%8,%9}, {%0,%1,%2,%3};" \
    : "+f"((d)[0]), "+f"((d)[1]), "+f"((d)[2]), "+f"((d)[3]) \
    : "r"((a)[0]), "r"((a)[1]), "r"((a)[2]), "r"((a)[3]), "r"((b)[0]), "r"((b)[1]))

__global__ __launch_bounds__(256, 1) void gi_gemm_mma_kernel(
    const float* __restrict__ bias)
{
    extern __shared__ char smem_raw[];
    const uint32_t sbase = smem_u32(smem_raw);
    const int tid  = threadIdx.x;
    const int lane = tid & 31;
    const int wid  = tid >> 5;
    const int wm   = wid >> 2;          // 0..1
    const int wn   = wid & 3;           // 0..3
    const int M0   = blockIdx.x * 128;  // M on x (512 wide)
    const int N0   = blockIdx.y * 128;  // N on y (12 wide) -> W planes L2-hot

    float acc[16][4];
#pragma unroll
    for (int i = 0; i < 16; ++i)
#pragma unroll
        for (int j = 0; j < 4; ++j) acc[i][j] = 0.0f;

    // ---- stage loader: 4 arrays x 2 chunks/thread, 16B cp.async each
    const int lrow = tid >> 2;           // 0..63
    const int lch  = (tid & 3) * 8;      // bf16 offset in row
    const __nv_bfloat16* __restrict__ srcs[4] = { g_a_hi, g_a_lo, g_w_hi, g_w_lo };

#define ISSUE_STAGE(kc, buf)                                                          \
    do {                                                                              \
        _Pragma("unroll")                                                             \
        for (int arr = 0; arr < 4; ++arr) {                                           \
            const int base_row = (arr < 2) ? M0 : N0;                                 \
            _Pragma("unroll")                                                         \
            for (int half = 0; half < 2; ++half) {                                    \
                const int row = lrow + half * 64;                                     \
                const __nv_bfloat16* g = srcs[arr]                                    \
                    + (size_t)(base_row + row) * INDIM + (kc) * BK + lch;             \
                const uint32_t s = sbase                                              \
                    + 2u * ((uint32_t)((buf) * 4 + arr) * ARR_ELEMS                   \
                            + (uint32_t)row * SROW + (uint32_t)lch);                  \
                asm volatile("cp.async.cg.shared.global [%0], [%1], 16;"              \
                             :: "r"(s), "l"(g));                                      \
            }                                                                         \
        }                                                                             \
        asm volatile("cp.async.commit_group;");                                       \
    } while (0)

    ISSUE_STAGE(0, 0);
    ISSUE_STAGE(1, 1);

    const int l15 = lane & 15;
    const uint32_t a_lanecol = 2u * ((uint32_t)(lane >> 4) * 8u);   // byte col offset
    const uint32_t a_lanerow = (uint32_t)(wm * 64 + l15);
    const uint32_t b_lanecol = 2u * ((uint32_t)(l15 >> 3) * 8u);
    const uint32_t b_lanerow = (uint32_t)(wn * 32 + (l15 & 7));

    for (int kc = 0; kc < 16; ++kc) {
        if (kc == 15) asm volatile("cp.async.wait_group 0;" ::: "memory");
        else          asm volatile("cp.async.wait_group 1;" ::: "memory");
        __syncthreads();
        if (kc + 2 < 16) ISSUE_STAGE(kc + 2, (kc + 2) % 3);

        const int buf = kc % 3;
        const uint32_t sb = sbase + 2u * (uint32_t)(buf * 4) * ARR_ELEMS;
#pragma unroll
        for (int ks = 0; ks < 2; ++ks) {
            uint32_t ahi[4][4], alo[4][4], bhi[4][2], blo[4][2];
            const uint32_t kb = 2u * (uint32_t)(ks * 16);
#pragma unroll
            for (int mi = 0; mi < 4; ++mi) {
                const uint32_t ah = sb + (a_lanerow + mi * 16) * (SROW * 2)
                                       + kb + a_lanecol;
                LDSM4(ahi[mi], ah);
                LDSM4(alo[mi], ah + 2u * ARR_ELEMS);
            }
#pragma unroll
            for (int ni = 0; ni < 4; ++ni) {
                const uint32_t bh = sb + 2u * 2u * ARR_ELEMS
                                       + (b_lanerow + ni * 8) * (SROW * 2)
                                       + kb + b_lanecol;
                LDSM2(bhi[ni], bh);
                LDSM2(blo[ni], bh + 2u * ARR_ELEMS);
            }
            // pass-major ordering: 16 independent mma between accumulator reuse
#pragma unroll
            for (int mi = 0; mi < 4; ++mi)
#pragma unroll
                for (int ni = 0; ni < 4; ++ni)
                    MMA16816(acc[mi * 4 + ni], ahi[mi], bhi[ni]);
#pragma unroll
            for (int mi = 0; mi < 4; ++mi)
#pragma unroll
                for (int ni = 0; ni < 4; ++ni)
                    MMA16816(acc[mi * 4 + ni], ahi[mi], blo[ni]);
#pragma unroll
            for (int mi = 0; mi < 4; ++mi)
#pragma unroll
                for (int ni = 0; ni < 4; ++ni)
                    MMA16816(acc[mi * 4 + ni], alo[mi], bhi[ni]);
        }
    }

    // ---- epilogue: direct fp32 stores + bias
    const int gr = lane >> 2;
    const int gc = (lane & 3) * 2;
#pragma unroll
    for (int mi = 0; mi < 4; ++mi) {
#pragma unroll
        for (int ni = 0; ni < 4; ++ni) {
            const int row = M0 + wm * 64 + mi * 16 + gr;
            const int col = N0 + wn * 32 + ni * 8 + gc;
            const float2 b2 = *(const float2*)(bias + col);
            float* o = g_gi + (size_t)row * G3 + col;
            float2 v0, v1;
            v0.x = acc[mi * 4 + ni][0] + b2.x;
            v0.y = acc[mi * 4 + ni][1] + b2.y;
            v1.x = acc[mi * 4 + ni][2] + b2.x;
            v1.y = acc[mi * 4 + ni][3] + b2.y;
            *(float2*)o = v0;
            *(float2*)(o + (size_t)8 * G3) = v1;
        }
    }
}

// ===========================================================================
// Phase 2: persistent recurrent kernel — PROVEN round-1 grid-barrier version
// ===========================================================================
__device__ __forceinline__ void cp_async16(float4* dst_smem, const float4* src) {
    unsigned d = (unsigned)__cvta_generic_to_shared(dst_smem);
    asm volatile("cp.async.cg.shared.global [%0], [%1], 16;" :: "r"(d), "l"(src));
}

__device__ __forceinline__ float sigmoidf_(float x) {
    return 1.0f / (1.0f + expf(-x));
}

__device__ __forceinline__ void grid_barrier(unsigned target, unsigned nblocks) {
    __syncthreads();
    if (threadIdx.x == 0) {
        __threadfence();
        unsigned prev = atomicAdd(&g_count, 1u);
        if (prev == nblocks - 1u) {
            *(volatile unsigned*)&g_count = 0u;
            __threadfence();
            *(volatile unsigned*)&g_phase = target;   // release
        } else {
            while (*(volatile unsigned*)&g_phase < target) { }
        }
        __threadfence();
    }
    __syncthreads();
}

// grid = 128 blocks x 128 threads. Block owns 4 hidden units (jb..jb+3).
// Warp jl handles hidden unit jb+jl for all 64 batches (lane = batch pair).
__global__ __launch_bounds__(128, 1) void gru_recurrent_kernel(
    const float* __restrict__ paddings,
    const float* __restrict__ W_hh,
    const float* __restrict__ b_hh,
    float* __restrict__ out)
{
    extern __shared__ float smemf[];
    float* sW   = smemf;                      // 12*512
    float* sh   = smemf + 12 * 512;           // 512*64  h(t-1), [hid][batch]
    float* sout = sh + HB;                    // 64*4

    const int tid = threadIdx.x;
    const int jl  = tid >> 5;
    const int bg  = tid & 31;
    const int jb  = blockIdx.x * 4;
    const int hid = jb + jl;
    const unsigned nblocks = gridDim.x;

    // Load this block's 12 W_hh rows (r,z,n for jb..jb+3) into SMEM once.
    for (int i = tid; i < 12 * 128; i += 128) {
        const int r = i >> 7;
        const int c = i & 127;
        const int grow = (r >> 2) * HID + jb + (r & 3);
        ((float4*)sW)[(size_t)r * 128 + c] =
            __ldg((const float4*)(W_hh + (size_t)grow * HID) + c);
    }
    const float bhr = __ldg(b_hh + hid);
    const float bhz = __ldg(b_hh + HID + hid);
    const float bhn = __ldg(b_hh + 2 * HID + hid);

    // h0 = 0 (each block zeroes its own 4 hidden rows of buffer 0)
    if (tid < 64) {
        float4 z4 = make_float4(0.f, 0.f, 0.f, 0.f);
        __stcg(((float4*)g_h[0]) + jb * 16 + tid, z4);
    }
    __threadfence();

    unsigned target = 1;
    grid_barrier(target, nblocks); ++target;

    int cur = 0;
    const float4* wr4 = (const float4*)(sW + (size_t)jl * 512);
    const float4* wz4 = (const float4*)(sW + (size_t)(4 + jl) * 512);
    const float4* wn4 = (const float4*)(sW + (size_t)(8 + jl) * 512);

    for (int t = 0; t < T_STEPS; ++t) {
        const int b0 = 2 * bg, b1 = b0 + 1;

        // Prefetch gi triplets + paddings early (streaming loads: evict-first)
        const float* gi_t = g_gi + (size_t)t * BATCH * G3;
        const float ir0 = __ldcs(gi_t + (size_t)b0 * G3 + hid);
        const float iz0 = __ldcs(gi_t + (size_t)b0 * G3 + HID + hid);
        const float in0 = __ldcs(gi_t + (size_t)b0 * G3 + 2 * HID + hid);
        const float ir1 = __ldcs(gi_t + (size_t)b1 * G3 + hid);
        const float iz1 = __ldcs(gi_t + (size_t)b1 * G3 + HID + hid);
        const float in1 = __ldcs(gi_t + (size_t)b1 * G3 + 2 * HID + hid);
        const float p0  = __ldg(paddings + t * BATCH + b0);
        const float p1  = __ldg(paddings + t * BATCH + b1);

        // Stage h (L2-coherent, L1-bypassing) in 4 pipelined chunks.
        const float4* hsrc = (const float4*)g_h[cur];
        float4* shd = (float4*)sh;
#pragma unroll
        for (int c = 0; c < 4; ++c) {
#pragma unroll
            for (int i = 0; i < 16; ++i) {
                const int idx = c * 2048 + i * 128 + tid;
                cp_async16(shd + idx, hsrc + idx);
            }
            asm volatile("cp.async.commit_group;");
        }

        float ar0 = 0.f, az0 = 0.f, an0 = 0.f;
        float ar1 = 0.f, az1 = 0.f, an1 = 0.f;
        const float2* h2 = ((const float2*)sh) + bg;

#pragma unroll
        for (int c = 0; c < 4; ++c) {
            if (c == 0)      asm volatile("cp.async.wait_group 3;");
            else if (c == 1) asm volatile("cp.async.wait_group 2;");
            else if (c == 2) asm volatile("cp.async.wait_group 1;");
            else             asm volatile("cp.async.wait_group 0;");
            __syncthreads();

            const int k4beg = c * 32;
#pragma unroll 4
            for (int k4 = k4beg; k4 < k4beg + 32; ++k4) {
                const float4 wr = wr4[k4];
                const float4 wz = wz4[k4];
                const float4 wn = wn4[k4];
                const float2 h0 = h2[(4 * k4 + 0) * 32];
                const float2 hA = h2[(4 * k4 + 1) * 32];
                const float2 hB = h2[(4 * k4 + 2) * 32];
                const float2 hC = h2[(4 * k4 + 3) * 32];
                ar0 += h0.x * wr.x; ar1 += h0.y * wr.x;
                az0 += h0.x * wz.x; az1 += h0.y * wz.x;
                an0 += h0.x * wn.x; an1 += h0.y * wn.x;
                ar0 += hA.x * wr.y; ar1 += hA.y * wr.y;
                az0 += hA.x * wz.y; az1 += hA.y * wz.y;
                an0 += hA.x * wn.y; an1 += hA.y * wn.y;
                ar0 += hB.x * wr.z; ar1 += hB.y * wr.z;
                az0 += hB.x * wz.z; az1 += hB.y * wz.z;
                an0 += hB.x * wn.z; an1 += hB.y * wn.z;
                ar0 += hC.x * wr.w; ar1 += hC.y * wr.w;
                az0 += hC.x * wz.w; az1 += hC.y * wz.w;
                an0 += hC.x * wn.w; an1 += hC.y * wn.w;
            }
        }

        // Gates + padding-aware carry.
        const float2 hp = *(const float2*)&sh[(size_t)hid * BATCH + b0];

        const float r0 = sigmoidf_(ir0 + ar0 + bhr);
        const float z0 = sigmoidf_(iz0 + az0 + bhz);
        const float n0 = tanhf(in0 + r0 * (an0 + bhn));
        const float hc0 = (1.f - z0) * n0 + z0 * hp.x;
        const float hn0 = p0 * hp.x + (1.f - p0) * hc0;

        const float r1 = sigmoidf_(ir1 + ar1 + bhr);
        const float z1 = sigmoidf_(iz1 + az1 + bhz);
        const float n1 = tanhf(in1 + r1 * (an1 + bhn));
        const float hc1 = (1.f - z1) * n1 + z1 * hp.y;
        const float hn1 = p1 * hp.y + (1.f - p1) * hc1;

        const int nxt = cur ^ 1;
        float2 hv; hv.x = hn0; hv.y = hn1;
        __stcg((float2*)&g_h[nxt][(size_t)hid * BATCH + b0], hv);

        sout[b0 * 4 + jl] = hn0;
        sout[b1 * 4 + jl] = hn1;
        __threadfence();      // make h_next globally visible before barrier
        __syncthreads();      // sout visible within block

        // Coalesced float4 output writes: outputs copy + states copy
        {
            const int copy = tid >> 6;       // 0 or 1
            const int b    = tid & 63;
            const float4 v = *(const float4*)&sout[b * 4];
            float* optr = out
                + (size_t)copy * ((size_t)BATCH * T_STEPS * HID)
                + (size_t)b * ((size_t)T_STEPS * HID)
                + (size_t)t * HID + jb;
            *(float4*)optr = v;
        }

        grid_barrier(target, nblocks); ++target;
        cur = nxt;
    }
}

// ---------------------------------------------------------------------------
// Launch
// ---------------------------------------------------------------------------
extern "C" void kernel_launch(void* const* d_in, const int* in_sizes, int n_in,
                              void* d_out, int out_size) {
    const float* x        = (const float*)d_in[0];   // [T,B,I]
    const float* paddings = (const float*)d_in[1];   // [T,B,1]
    const float* W_ih     = (const float*)d_in[2];   // [3H,I]
    const float* W_hh     = (const float*)d_in[3];   // [3H,H]
    const float* b_ih     = (const float*)d_in[4];   // [3H]
    const float* b_hh     = (const float*)d_in[5];   // [3H]
    float* out            = (float*)d_out;           // [2][B][T][H]

    cudaFuncSetAttribute(gi_gemm_mma_kernel,
                         cudaFuncAttributeMaxDynamicSharedMemorySize, GEMM_SMEM);
    const int rec_smem = (12 * 512 + HB + BATCH * 4) * sizeof(float);   // 156,672 B
    cudaFuncSetAttribute(gru_recurrent_kernel,
                         cudaFuncAttributeMaxDynamicSharedMemorySize, rec_smem);

    reset_barrier_kernel<<<1, 1>>>();

    convert_kernel<<<2048, 256>>>(x, W_ih);

    dim3 gemm_grid(TBROWS / 128, G3 / 128);   // 512 x 12 (M on x, N on y)
    gi_gemm_mma_kernel<<<gemm_grid, 256, GEMM_SMEM>>>(b_ih);

    gru_recurrent_kernel<<<128, 128, rec_smem>>>(paddings, W_hh, b_hh, out);
}